// round 6
// baseline (speedup 1.0000x reference)
#include <cuda_runtime.h>
#include <cuda_bf16.h>
#include <cstdint>

// Problem constants
#define BATCH   2
#define NPTS    2048
#define CIN     64
#define COUT    128
#define GRIDV   12
#define NVOX    (GRIDV*GRIDV*GRIDV)   // 1728
#define NOFF    27
#define TM      32                    // points per conv block
#define NBLK    (BATCH*NPTS/TM)       // 128
#define NROWS   (BATCH*NVOX)          // 3456
#define ZROW    NROWS                 // dedicated zero row index

// Scratch (device globals; no allocation allowed)
__device__ float g_aggF[NROWS * CIN];
// aggF converted to bf16 hi/lo rows: [row][ci] bf16, 128B per row (+1 zero row)
__device__ __align__(16) unsigned char g_aggH[(NROWS + 1) * 128];
__device__ __align__(16) unsigned char g_aggL[(NROWS + 1) * 128];
// W n-major bf16 hi/lo: addr = ((o*2+h)*128 + n)*128 + k*2
__device__ __align__(16) unsigned char g_Wn[NOFF * 2 * COUT * 128];

// ---------------------------------------------------------------------------
// Helpers
// ---------------------------------------------------------------------------
#define CP_ASYNC16(dst_u32, src_ptr) \
    asm volatile("cp.async.cg.shared.global [%0], [%1], 16;" :: "r"(dst_u32), "l"(src_ptr))
#define CP_ASYNC_COMMIT() asm volatile("cp.async.commit_group;" ::: "memory")
#define CP_ASYNC_WAIT0()  asm volatile("cp.async.wait_group 0;" ::: "memory")

__device__ __forceinline__ uint32_t smem_u32(const void* p) {
    uint32_t a;
    asm("{ .reg .u64 t; cvta.to.shared.u64 t, %1; cvt.u32.u64 %0, t; }" : "=r"(a) : "l"(p));
    return a;
}

__device__ __forceinline__ void ldsm_x4(uint32_t* r, uint32_t addr) {
    asm volatile("ldmatrix.sync.aligned.m8n8.x4.shared.b16 {%0,%1,%2,%3}, [%4];"
                 : "=r"(r[0]), "=r"(r[1]), "=r"(r[2]), "=r"(r[3]) : "r"(addr));
}

__device__ __forceinline__ void mma_bf16(float* c, const uint32_t* a, uint32_t b0, uint32_t b1) {
    asm volatile(
        "mma.sync.aligned.m16n8k16.row.col.f32.bf16.bf16.f32 "
        "{%0,%1,%2,%3}, {%4,%5,%6,%7}, {%8,%9}, {%0,%1,%2,%3};"
        : "+f"(c[0]), "+f"(c[1]), "+f"(c[2]), "+f"(c[3])
        : "r"(a[0]), "r"(a[1]), "r"(a[2]), "r"(a[3]), "r"(b0), "r"(b1));
}

__device__ __forceinline__ uint32_t pack_hi(float f0, float f1) {
    return ((uint32_t)__bfloat16_as_ushort(__float2bfloat16(f1)) << 16)
         | __bfloat16_as_ushort(__float2bfloat16(f0));
}
__device__ __forceinline__ uint32_t pack_lo(float f0, float f1) {
    float r0 = f0 - __bfloat162float(__float2bfloat16(f0));
    float r1 = f1 - __bfloat162float(__float2bfloat16(f1));
    return ((uint32_t)__bfloat16_as_ushort(__float2bfloat16(r1)) << 16)
         | __bfloat16_as_ushort(__float2bfloat16(r0));
}

// ---------------------------------------------------------------------------
// Kernel 1: zero aggF + pack W n-major bf16 hi/lo
// blocks [0,216): zero aggF (216*256 float4)
// blocks [216,1080): one thread per (o,h,n,k2): pack 2 k values
// ---------------------------------------------------------------------------
__global__ void prep_kernel(const float* __restrict__ weight) {
    int bid = blockIdx.x;
    if (bid < 216) {
        int t = bid * 256 + threadIdx.x;
        ((float4*)g_aggF)[t] = make_float4(0.f, 0.f, 0.f, 0.f);
    } else {
        int i = (bid - 216) * 256 + threadIdx.x;   // 0..221183
        int k2 = i & 31;
        int n  = (i >> 5) & 127;
        int h  = (i >> 12) & 1;
        int o  = i >> 13;                          // 0..26
        float w0 = weight[(o * CIN + 2 * k2) * COUT + n];
        float w1 = weight[(o * CIN + 2 * k2 + 1) * COUT + n];
        uint32_t pk = (h == 0) ? pack_hi(w0, w1) : pack_lo(w0, w1);
        *(uint32_t*)(g_Wn + ((size_t)(o * 2 + h) * 128 + n) * 128 + k2 * 4) = pk;
    }
}

// ---------------------------------------------------------------------------
// Kernel 2: scatter-add features into per-voxel bins
// ---------------------------------------------------------------------------
__global__ void aggregate_kernel(const float* __restrict__ points,
                                 const float* __restrict__ feats) {
    int gid = blockIdx.x * blockDim.x + threadIdx.x;
    if (gid >= BATCH * NPTS * CIN) return;
    int c = gid & (CIN - 1);
    int p = gid >> 6;
    int b = p / NPTS;
    int vx = (int)points[p * 3 + 0];
    int vy = (int)points[p * 3 + 1];
    int vz = (int)points[p * 3 + 2];
    if ((unsigned)vx >= GRIDV || (unsigned)vy >= GRIDV || (unsigned)vz >= GRIDV) return;
    int lin = (vx * GRIDV + vy) * GRIDV + vz;
    atomicAdd(&g_aggF[(b * NVOX + lin) * CIN + c], feats[gid]);
}

// ---------------------------------------------------------------------------
// Kernel 3: convert aggF -> bf16 hi/lo rows (once per voxel), plus zero row
// one thread per (row, ci-pair): 3457*32 threads
// ---------------------------------------------------------------------------
__global__ void convert_kernel() {
    int gid = blockIdx.x * blockDim.x + threadIdx.x;
    if (gid >= (NROWS + 1) * 32) return;
    int row = gid >> 5;
    int c2  = gid & 31;
    uint32_t hp = 0, lp = 0;
    if (row < NROWS) {
        float2 v = *(const float2*)(g_aggF + (size_t)row * CIN + c2 * 2);
        hp = pack_hi(v.x, v.y);
        lp = pack_lo(v.x, v.y);
    }
    *(uint32_t*)(g_aggH + (size_t)row * 128 + c2 * 4) = hp;
    *(uint32_t*)(g_aggL + (size_t)row * 128 + c2 * 4) = lp;
}

// ---------------------------------------------------------------------------
// Kernel 4: mma.sync conv, all staging via cp.async, frags via ldmatrix.
// 128 blocks x 256 threads (8 warps). Tile 32 points x 128 couts.
// Warp (wm,wn) in 2x4: 16 rows x 32 couts. C register-resident.
// smem rows padded to 144B for conflict-free LDSM.
// Layout:
//   sW[buf][h][n 0..127][144]   2 x 36864
//   sA[buf][h][m 0..31][144]    2 x 9216
//   svox[384]
// ---------------------------------------------------------------------------
#define RSTR   144
#define WBUF   (2 * COUT * RSTR)       // 36864
#define ABUF   (2 * TM * RSTR)         // 9216
#define SMO_W  0
#define SMO_A  (2 * WBUF)              // 73728
#define SMO_VOX (SMO_A + 2 * ABUF)     // 92160
#define SMEM_TOTAL (SMO_VOX + 512)     // 92672

__global__ __launch_bounds__(256, 1)
void conv_mma_kernel(const float* __restrict__ points,
                     const float* __restrict__ bias,
                     float* __restrict__ out) {
    extern __shared__ __align__(16) unsigned char smem[];
    int* svox = (int*)(smem + SMO_VOX);

    const int tid  = threadIdx.x;
    const int warp = tid >> 5;
    const int lane = tid & 31;
    const int wm   = warp >> 2;      // 0..1 : rows [wm*16, +16)
    const int wn   = warp & 3;       // 0..3 : couts [wn*32, +32)
    const int grp  = lane >> 2;      // 0..7
    const int tig  = lane & 3;       // 0..3

    const int p0 = blockIdx.x * TM;
    const int b  = p0 >> 11;         // / NPTS

    if (tid < TM) {
        int p = p0 + tid;
        svox[tid]          = (int)points[p * 3 + 0];
        svox[TM + tid]     = (int)points[p * 3 + 1];
        svox[2 * TM + tid] = (int)points[p * 3 + 2];
    }
    __syncthreads();

    const uint32_t sb = smem_u32(smem);

    // ---- A staging geometry: thread -> (h, row, 16B chunk) ----
    // 2 cp.async per thread: (arow, acig) hi + lo
    const int arow = tid >> 3;           // 0..31
    const int acig = tid & 7;            // 0..7
    const int avx = svox[arow], avy = svox[TM + arow], avz = svox[2 * TM + arow];

    auto issueA = [&](int o, int bi) {
        int dx = o / 9 - 1, dy = (o / 3) % 3 - 1, dz = o % 3 - 1;
        int nx = avx + dx, ny = avy + dy, nz = avz + dz;
        int rowIdx = ZROW;
        if ((unsigned)nx < GRIDV && (unsigned)ny < GRIDV && (unsigned)nz < GRIDV)
            rowIdx = b * NVOX + (nx * GRIDV + ny) * GRIDV + nz;
        const unsigned char* srcH = g_aggH + (size_t)rowIdx * 128 + acig * 16;
        const unsigned char* srcL = g_aggL + (size_t)rowIdx * 128 + acig * 16;
        uint32_t dstH = sb + SMO_A + bi * ABUF + arow * RSTR + acig * 16;
        CP_ASYNC16(dstH, srcH);
        CP_ASYNC16(dstH + TM * RSTR, srcL);
    };
    // W staging: 2048 chunks / 256 threads = 8 per thread
    auto issueW = [&](int o, int bi) {
        #pragma unroll
        for (int i = 0; i < 8; i++) {
            int ch = tid + i * 256;          // 0..2047
            int h  = ch >> 10;
            int n  = (ch >> 3) & 127;
            int kc = ch & 7;
            const unsigned char* src = g_Wn + ((size_t)(o * 2 + h) * 128 + n) * 128 + kc * 16;
            uint32_t dst = sb + SMO_W + bi * WBUF + h * (COUT * RSTR) + n * RSTR + kc * 16;
            CP_ASYNC16(dst, src);
        }
    };

    float c[16];
    #pragma unroll
    for (int i = 0; i < 16; i++) c[i] = 0.f;

    // ---- prologue ----
    issueW(0, 0);
    issueA(0, 0);
    CP_ASYNC_COMMIT();
    CP_ASYNC_WAIT0();
    __syncthreads();

    // ldmatrix lane addressing (constant per thread)
    // A: row = wm*16 + ((lane>>3)&1)*8 + (lane&7), kbyte = (lane>>4)*16
    const uint32_t aAddrBase = sb + SMO_A
        + (uint32_t)(wm * 16 + ((lane >> 3) & 1) * 8 + (lane & 7)) * RSTR
        + ((lane >> 4) & 1) * 16;
    // B: n = nb + ((lane>>4)&1)*8 + (lane&7), kbyte = ((lane>>3)&1)*16
    const uint32_t bAddrBase = sb + SMO_W
        + (uint32_t)(wn * 32 + ((lane >> 4) & 1) * 8 + (lane & 7)) * RSTR
        + ((lane >> 3) & 1) * 16;

    for (int o = 0; o < NOFF; o++) {
        const int cur = o & 1;
        const int nxt = cur ^ 1;
        const bool more = (o + 1 < NOFF);

        if (more) {
            issueW(o + 1, nxt);
            issueA(o + 1, nxt);
            CP_ASYNC_COMMIT();
        }

        // ---- mma: 3 passes (Ah*Wh, Ah*Wl, Al*Wh) x 4 kk x 4 n-frags ----
        #pragma unroll
        for (int pass = 0; pass < 3; pass++) {
            const uint32_t aB = aAddrBase + (uint32_t)cur * ABUF
                              + ((pass == 2) ? (uint32_t)(TM * RSTR) : 0u);
            const uint32_t bB = bAddrBase + (uint32_t)cur * WBUF
                              + ((pass == 1) ? (uint32_t)(COUT * RSTR) : 0u);
            #pragma unroll
            for (int kk = 0; kk < 4; kk++) {
                uint32_t a[4], b0[4], b1[4];
                ldsm_x4(a,  aB + kk * 32);
                ldsm_x4(b0, bB + kk * 32);               // n-frags 0,1 (n +0..15)
                ldsm_x4(b1, bB + 16 * RSTR + kk * 32);   // n-frags 2,3 (n +16..31)
                mma_bf16(&c[0],  a, b0[0], b0[1]);
                mma_bf16(&c[4],  a, b0[2], b0[3]);
                mma_bf16(&c[8],  a, b1[0], b1[1]);
                mma_bf16(&c[12], a, b1[2], b1[3]);
            }
        }

        if (more) CP_ASYNC_WAIT0();
        __syncthreads();
    }

    // ---- epilogue: C frags + bias -> out ----
    #pragma unroll
    for (int j = 0; j < 4; j++) {
        int col = wn * 32 + j * 8 + tig * 2;
        float2 bv = *(const float2*)(bias + col);
        int r0 = p0 + wm * 16 + grp;
        float2 o0 = make_float2(c[j*4+0] + bv.x, c[j*4+1] + bv.y);
        float2 o1 = make_float2(c[j*4+2] + bv.x, c[j*4+3] + bv.y);
        *(float2*)(out + (size_t)r0 * COUT + col)       = o0;
        *(float2*)(out + (size_t)(r0 + 8) * COUT + col) = o1;
    }
}

// ---------------------------------------------------------------------------
extern "C" void kernel_launch(void* const* d_in, const int* in_sizes, int n_in,
                              void* d_out, int out_size) {
    const float* points  = (const float*)d_in[0];   // (B, N, 3)
    const float* feats   = (const float*)d_in[1];   // (B, N, CIN)
    const float* weight  = (const float*)d_in[2];   // (3,3,3,CIN,COUT)
    const float* bias    = (const float*)d_in[3];   // (COUT)
    float* out = (float*)d_out;                     // (B, N, COUT)

    cudaFuncSetAttribute(conv_mma_kernel,
                         cudaFuncAttributeMaxDynamicSharedMemorySize, SMEM_TOTAL);

    // 1) zero agg scratch + pack W (n-major bf16 hi/lo)
    prep_kernel<<<1080, 256>>>(weight);
    // 2) per-voxel feature aggregation (fp32 atomics)
    aggregate_kernel<<<(BATCH * NPTS * CIN + 255) / 256, 256>>>(points, feats);
    // 3) convert aggF to bf16 hi/lo rows (+ zero row)
    convert_kernel<<<((NROWS + 1) * 32 + 255) / 256, 256>>>();
    // 4) tensor-core conv + bias, cp.async double-buffered, ldmatrix frags
    conv_mma_kernel<<<NBLK, 256, SMEM_TOTAL>>>(points, bias, out);
}